// round 17
// baseline (speedup 1.0000x reference)
#include <cuda_runtime.h>
#include <cuda_fp16.h>
#include <cstdint>

// ---------------------------------------------------------------------------
// Problem constants
// ---------------------------------------------------------------------------
#define BATCH   4
#define NSEQ    2048
#define DIM     1024
#define HEADS   16
#define HDIM    64
#define M_ROWS  8192
#define N_COLS  3072
#define K_DIM   1024
#define SCALE   32.0f

// qkv GEMM tiling (round-6 proven: CTA 128x128, 8 warps 4x2, 3 stages, 2 CTAs/SM)
#define QBM 128
#define QBN 128
#define KCH 64
#define NCHUNK (K_DIM / KCH)
#define STAGE_BYTES 32768
#define NSTAGE 3
#define SMEM_DYN (NSTAGE * STAGE_BYTES)

// kv_partial: 2 groups/CTA, each 3-stage ring of 8KB
#define KVP_STAGE 8192
#define KVP_GROUP_SMEM (3 * KVP_STAGE)          // 24576 per group
#define KVP_SMEM (2 * KVP_GROUP_SMEM)           // 49152

#define OUT_SMEM 32768               // q 16KB + KVT hi 8KB + KVT lo 8KB

// ---------------------------------------------------------------------------
// Scratch (device globals — allocation-free per harness rules)
// ---------------------------------------------------------------------------
__device__ __align__(16) __half g_Ah[(size_t)M_ROWS * K_DIM];      // fp16(x)
__device__ __align__(16) __half g_Bh[(size_t)N_COLS * K_DIM];      // W^T permuted fp16
__device__ float g_biasP[N_COLS];
// Y packed by (plane, pair): index ((t*64 + b*16 + h) * 2048 + n) * 64 + d
__device__ __align__(16) __half g_Ypack[(size_t)3 * 64 * NSEQ * HDIM];
__device__ float g_KVp[64 * 8 * HDIM * HDIM];                      // KV^T partials [d2][d1]
__device__ __align__(16) __half g_KVThi[64 * HDIM * HDIM];
__device__ __align__(16) __half g_KVTlo[64 * HDIM * HDIM];

// ---------------------------------------------------------------------------
// Inline PTX (valid on base sm_103 target)
// ---------------------------------------------------------------------------
__device__ __forceinline__ uint32_t smem_u32(const void* p) {
    uint32_t a;
    asm("{ .reg .u64 t; cvta.to.shared.u64 t, %1; cvt.u32.u64 %0, t; }" : "=r"(a) : "l"(p));
    return a;
}
__device__ __forceinline__ void cp16(uint32_t dst, const void* src) {
    asm volatile("cp.async.cg.shared.global [%0], [%1], 16;" :: "r"(dst), "l"(src));
}
__device__ __forceinline__ void ldsm4(uint32_t* r, uint32_t addr) {
    asm volatile("ldmatrix.sync.aligned.m8n8.x4.shared.b16 {%0,%1,%2,%3}, [%4];"
        : "=r"(r[0]), "=r"(r[1]), "=r"(r[2]), "=r"(r[3]) : "r"(addr));
}
__device__ __forceinline__ void ldsm4t(uint32_t* r, uint32_t addr) {
    asm volatile("ldmatrix.sync.aligned.m8n8.x4.trans.shared.b16 {%0,%1,%2,%3}, [%4];"
        : "=r"(r[0]), "=r"(r[1]), "=r"(r[2]), "=r"(r[3]) : "r"(addr));
}
__device__ __forceinline__ void hmma(float* d, const uint32_t* a, const uint32_t* b) {
    asm volatile("mma.sync.aligned.m16n8k16.row.col.f32.f16.f16.f32 "
        "{%0,%1,%2,%3}, {%4,%5,%6,%7}, {%8,%9}, {%0,%1,%2,%3};"
        : "+f"(d[0]), "+f"(d[1]), "+f"(d[2]), "+f"(d[3])
        : "r"(a[0]), "r"(a[1]), "r"(a[2]), "r"(a[3]), "r"(b[0]), "r"(b[1]));
}
__device__ __forceinline__ void barg(int id) {
    asm volatile("bar.sync %0, 128;" :: "r"(id) : "memory");
}

// ---------------------------------------------------------------------------
// conv_x: fp32 x -> fp16 (no smem -> full occupancy)
// ---------------------------------------------------------------------------
__global__ __launch_bounds__(256)
void conv_x(const float4* __restrict__ x)
{
    size_t i = (size_t)blockIdx.x * 256 + threadIdx.x;
    float4 v = x[i];
    __half h[4];
    h[0] = __float2half(v.x); h[1] = __float2half(v.y);
    h[2] = __float2half(v.z); h[3] = __float2half(v.w);
    *(uint2*)(g_Ah + 4 * i) = *(uint2*)h;
}

// ---------------------------------------------------------------------------
// conv_w: W [k][c] -> permuted transposed fp16 g_Bh[c'][k]; folds bias permute
// c = h*192 + d*3 + t  ->  c' = t*1024 + h*64 + d
// ---------------------------------------------------------------------------
__global__ __launch_bounds__(256)
void conv_w(const float* __restrict__ W, const float* __restrict__ bias)
{
    __shared__ float tile[32][193];
    const int h  = blockIdx.x;
    const int k0 = blockIdx.y * 32;
    const int tid = threadIdx.x;

    if (blockIdx.y == 0 && tid < 192) {
        int d = tid & 63, t = tid >> 6;
        g_biasP[t * 1024 + h * 64 + d] = bias[h * 192 + d * 3 + t];
    }

    for (int e = tid; e < 32 * 192; e += 256) {
        int r = e / 192, cc = e % 192;
        tile[r][cc] = W[(size_t)(k0 + r) * N_COLS + h * 192 + cc];
    }
    __syncthreads();

    for (int e = tid; e < 3 * 64 * 32; e += 256) {
        int t = e >> 11;
        int rem = e & 2047;
        int d = rem >> 5, kk = rem & 31;
        float v = tile[kk][d * 3 + t];
        g_Bh[(size_t)(t * 1024 + h * 64 + d) * K_DIM + k0 + kk] = __float2half(v);
    }
}

// ---------------------------------------------------------------------------
// Kernel A: qkv projection via mma.sync fp16; epilogue stores PACKED layout
// grid (24, 64), 256 threads (8 warps, 4x2), 2 CTAs/SM  (round-16 exact)
// ---------------------------------------------------------------------------
__device__ __forceinline__ void load_chunk(uint32_t stage_sb, int rowBase, int colBase,
                                           int k0, int tid)
{
#pragma unroll
    for (int i = 0; i < 4; i++) {
        int o = tid + i * 256;
        int r = o >> 3, ch = o & 7;
        cp16(stage_sb + r * 128 + ((ch ^ (r & 7)) << 4),
             g_Ah + (size_t)(rowBase + r) * K_DIM + k0 + ch * 8);
    }
#pragma unroll
    for (int i = 0; i < 4; i++) {
        int o = tid + i * 256;
        int r = o >> 3, ch = o & 7;
        cp16(stage_sb + 16384 + r * 128 + ((ch ^ (r & 7)) << 4),
             g_Bh + (size_t)(colBase + r) * K_DIM + k0 + ch * 8);
    }
}

__global__ __launch_bounds__(256, 2)
void qkv_mma()
{
    extern __shared__ char smem[];
    const uint32_t sb = smem_u32(smem);
    const int tid = threadIdx.x;
    const int wid = tid >> 5, lid = tid & 31;
    const int warp_m = wid >> 1, warp_n = wid & 1;
    const int rowBase = blockIdx.y * QBM;
    const int colBase = blockIdx.x * QBN;

    float acc[2][8][4];
#pragma unroll
    for (int mt = 0; mt < 2; mt++)
#pragma unroll
        for (int nt = 0; nt < 8; nt++)
#pragma unroll
            for (int j = 0; j < 4; j++) acc[mt][nt][j] = 0.0f;

#pragma unroll
    for (int c = 0; c < NSTAGE; c++) {
        load_chunk(sb + c * STAGE_BYTES, rowBase, colBase, c * KCH, tid);
        asm volatile("cp.async.commit_group;" ::: "memory");
    }

    const uint32_t aRowOff = (uint32_t)(warp_m * 32 + (lid & 15)) * 128;
    const uint32_t bRowOff = (uint32_t)(warp_n * 64 + (lid & 7) + ((lid >> 4) & 1) * 8) * 128;
    const int xorC   = lid & 7;
    const int chSelA = lid >> 4;
    const int chSelB = (lid >> 3) & 1;

    for (int c = 0; c < NCHUNK; c++) {
        asm volatile("cp.async.wait_group 2;" ::: "memory");
        __syncthreads();
        const uint32_t st = sb + (uint32_t)(c % NSTAGE) * STAGE_BYTES;

#pragma unroll
        for (int ks = 0; ks < 4; ks++) {
            const uint32_t chA = (uint32_t)((ks * 2 + chSelA) ^ xorC) << 4;
            const uint32_t chB = (uint32_t)((ks * 2 + chSelB) ^ xorC) << 4;
            uint32_t ah[2][4];
#pragma unroll
            for (int mt = 0; mt < 2; mt++)
                ldsm4(ah[mt], st + aRowOff + mt * (16 * 128) + chA);
            uint32_t bh[4][4];
#pragma unroll
            for (int p = 0; p < 4; p++)
                ldsm4(bh[p], st + 16384 + bRowOff + p * (16 * 128) + chB);
#pragma unroll
            for (int mt = 0; mt < 2; mt++)
#pragma unroll
                for (int p = 0; p < 4; p++) {
                    hmma(acc[mt][2 * p + 0], ah[mt], &bh[p][0]);
                    hmma(acc[mt][2 * p + 1], ah[mt], &bh[p][2]);
                }
        }
        __syncthreads();
        if (c + NSTAGE < NCHUNK)
            load_chunk(st, rowBase, colBase, (c + NSTAGE) * KCH, tid);
        asm volatile("cp.async.commit_group;" ::: "memory");
    }

    // Epilogue: + bias -> PACKED fp16 Y
    const int ec0 = colBase + warp_n * 64;
    const int t_  = ec0 >> 10;
    const int h_  = (ec0 & 1023) >> 6;
    const int b_  = rowBase >> 11;
    const int nBase = (rowBase & 2047) + warp_m * 32 + (lid >> 2);
    const int dBase = (lid & 3) * 2;
    __half* ybase = g_Ypack + ((size_t)(t_ * 64 + b_ * 16 + h_) * NSEQ) * HDIM;

    float2 bb[8];
#pragma unroll
    for (int nt = 0; nt < 8; nt++) bb[nt] = *(const float2*)&g_biasP[ec0 + dBase + nt * 8];
#pragma unroll
    for (int mt = 0; mt < 2; mt++) {
        const int n0 = nBase + mt * 16;
#pragma unroll
        for (int nt = 0; nt < 8; nt++) {
            __half2 v0 = __floats2half2_rn(acc[mt][nt][0] + bb[nt].x,
                                           acc[mt][nt][1] + bb[nt].y);
            __half2 v1 = __floats2half2_rn(acc[mt][nt][2] + bb[nt].x,
                                           acc[mt][nt][3] + bb[nt].y);
            *(__half2*)&ybase[(size_t)n0 * HDIM + dBase + nt * 8] = v0;
            *(__half2*)&ybase[(size_t)(n0 + 8) * HDIM + dBase + nt * 8] = v1;
        }
    }
}

// ---------------------------------------------------------------------------
// Kernel B: KV^T partials, 2 independent 128-thread groups per CTA
// grid (64, 4), 256 threads, 48KB smem; group g handles split 2*by+g
// ---------------------------------------------------------------------------
__device__ __forceinline__ void kvp_load_sub(uint32_t stg, const __half* kbase,
                                             const __half* vbase, int n0, int s, int wtid)
{
#pragma unroll
    for (int i = 0; i < 4; i++) {
        int o = wtid + i * 128;
        int t = o >> 8;                     // 0 = v, 1 = k
        int r = (o >> 3) & 31;
        int ch = o & 7;
        uint32_t sw = stg + t * 4096 + r * 128 + ((ch ^ (r & 7)) << 4);
        const __half* src = (t ? kbase : vbase) + (size_t)(n0 + s * 32 + r) * HDIM + ch * 8;
        cp16(sw, src);
    }
}

__global__ __launch_bounds__(256)
void kv_partial()
{
    extern __shared__ char smc[];
    const int pair = blockIdx.x;
    const int tid  = threadIdx.x;
    const int grp  = tid >> 7;              // 0 / 1
    const int wtid = tid & 127;
    const int gwid = (wtid >> 5);           // warp within group: 0..3
    const int lid  = tid & 31;
    const int split = blockIdx.y * 2 + grp; // 0..7
    const int barId = 1 + grp;

    const uint32_t sbase = smem_u32(smc) + (uint32_t)grp * KVP_GROUP_SMEM;
    const int n0 = split * 256;
    const __half* kbase = g_Ypack + ((size_t)(64 + pair) * NSEQ) * HDIM;
    const __half* vbase = g_Ypack + ((size_t)(128 + pair) * NSEQ) * HDIM;

    kvp_load_sub(sbase,             kbase, vbase, n0, 0, wtid);
    asm volatile("cp.async.commit_group;" ::: "memory");
    kvp_load_sub(sbase + KVP_STAGE, kbase, vbase, n0, 1, wtid);
    asm volatile("cp.async.commit_group;" ::: "memory");

    float acc[4][2][4];
#pragma unroll
    for (int mt = 0; mt < 4; mt++)
#pragma unroll
        for (int bn = 0; bn < 2; bn++)
#pragma unroll
            for (int j = 0; j < 4; j++) acc[mt][bn][j] = 0.0f;

    const int krA = (lid & 7) | ((lid & 16) >> 1);
    const int mSel = (lid >> 3) & 1;
    const int krB = lid & 15;
    const int nSel = lid >> 4;
    const int xA = krA & 7;
    const int xB = krB & 7;

    for (int s = 0; s < 8; s++) {
        if (s < 7) { asm volatile("cp.async.wait_group 1;" ::: "memory"); }
        else       { asm volatile("cp.async.wait_group 0;" ::: "memory"); }
        barg(barId);

        if (s + 2 < 8) {
            kvp_load_sub(sbase + (uint32_t)((s + 2) % 3) * KVP_STAGE,
                         kbase, vbase, n0, s + 2, wtid);
            asm volatile("cp.async.commit_group;" ::: "memory");
        }

        const uint32_t stV = sbase + (uint32_t)(s % 3) * KVP_STAGE;
        const uint32_t stK = stV + 4096;
#pragma unroll
        for (int kl = 0; kl < 2; kl++) {
            const int rowA = kl * 16 + krA;
            const int rowB = kl * 16 + krB;
            uint32_t a[4][4];
#pragma unroll
            for (int mt = 0; mt < 4; mt++) {
                uint32_t ch = (uint32_t)((mt * 2 + mSel) ^ xA) << 4;
                ldsm4t(a[mt], stV + rowA * 128 + ch);
            }
            uint32_t bf[4];
            {
                uint32_t ch = (uint32_t)((gwid * 2 + nSel) ^ xB) << 4;
                ldsm4t(bf, stK + rowB * 128 + ch);
            }
#pragma unroll
            for (int mt = 0; mt < 4; mt++) {
                hmma(acc[mt][0], a[mt], &bf[0]);
                hmma(acc[mt][1], a[mt], &bf[2]);
            }
        }
        barg(barId);   // group done reading stage s before it is overwritten
    }

    float* dst = g_KVp + ((size_t)pair * 8 + split) * (HDIM * HDIM);
    const int d1c = gwid * 16 + (lid & 3) * 2;
#pragma unroll
    for (int mt = 0; mt < 4; mt++) {
        const int d2r = mt * 16 + (lid >> 2);
#pragma unroll
        for (int bn = 0; bn < 2; bn++) {
            *(float2*)&dst[(size_t)d2r * HDIM + d1c + bn * 8] =
                *(float2*)&acc[mt][bn][0];
            *(float2*)&dst[(size_t)(d2r + 8) * HDIM + d1c + bn * 8] =
                *(float2*)&acc[mt][bn][2];
        }
    }
}

// ---------------------------------------------------------------------------
// kv_reduce: float4-vectorized; sum 8 splits, scale, emit fp16 hi+lo
// ---------------------------------------------------------------------------
__global__ __launch_bounds__(256)
void kv_reduce()
{
    int idx = blockIdx.x * 256 + threadIdx.x;
    int pair = idx >> 10, off = idx & 1023;
    const float4* src = (const float4*)g_KVp + (size_t)pair * 8 * 1024 + off;
    float4 s = make_float4(0.f, 0.f, 0.f, 0.f);
#pragma unroll
    for (int k = 0; k < 8; k++) {
        float4 v = src[(size_t)k * 1024];
        s.x += v.x; s.y += v.y; s.z += v.z; s.w += v.w;
    }
    s.x *= SCALE; s.y *= SCALE; s.z *= SCALE; s.w *= SCALE;

    __half hi[4], lo[4];
    hi[0] = __float2half(s.x); lo[0] = __float2half(s.x - __half2float(hi[0]));
    hi[1] = __float2half(s.y); lo[1] = __float2half(s.y - __half2float(hi[1]));
    hi[2] = __float2half(s.z); lo[2] = __float2half(s.z - __half2float(hi[2]));
    hi[3] = __float2half(s.w); lo[3] = __float2half(s.w - __half2float(hi[3]));
    *(uint2*)(g_KVThi + 4 * (size_t)idx) = *(uint2*)hi;
    *(uint2*)(g_KVTlo + 4 * (size_t)idx) = *(uint2*)lo;
}

// ---------------------------------------------------------------------------
// Kernel C: out = q @ KV via HMMA, 128-row tiles (round-16 exact)
// grid (64 pairs, 16 chunks of 128 rows), 256 threads
// ---------------------------------------------------------------------------
__global__ __launch_bounds__(256)
void out_gemm(float* __restrict__ out)
{
    extern __shared__ char smc[];
    const uint32_t sq  = smem_u32(smc);
    const uint32_t sbh = sq + 16384;
    const uint32_t sbl = sbh + 8192;

    const int pair = blockIdx.x;
    const int nc   = blockIdx.y;
    const int tid = threadIdx.x;
    const int wid = tid >> 5, lid = tid & 31;

    const __half* qbase = g_Ypack + ((size_t)pair * NSEQ) * HDIM;
    const int n0 = nc * 128;

#pragma unroll
    for (int i = 0; i < 4; i++) {
        int o = tid + i * 256;
        int r = o >> 3, ch = o & 7;
        uint32_t sw = r * 128 + ((ch ^ (r & 7)) << 4);
        cp16(sq + sw, qbase + (size_t)(n0 + r) * HDIM + ch * 8);
    }
    const __half* kvh = g_KVThi + (size_t)pair * 4096;
    const __half* kvl = g_KVTlo + (size_t)pair * 4096;
#pragma unroll
    for (int i = 0; i < 2; i++) {
        int o = tid + i * 256;
        int r = o >> 3, ch = o & 7;
        uint32_t sw = r * 128 + ((ch ^ (r & 7)) << 4);
        cp16(sbh + sw, kvh + r * 64 + ch * 8);
        cp16(sbl + sw, kvl + r * 64 + ch * 8);
    }
    asm volatile("cp.async.commit_group;" ::: "memory");
    asm volatile("cp.async.wait_group 0;" ::: "memory");
    __syncthreads();

    float acc[8][4];
#pragma unroll
    for (int nt = 0; nt < 8; nt++)
#pragma unroll
        for (int j = 0; j < 4; j++) acc[nt][j] = 0.0f;

    const uint32_t aRowOff = (uint32_t)(wid * 16 + (lid & 15)) * 128;
    const uint32_t bRowOff = (uint32_t)((lid & 7) + ((lid >> 4) & 1) * 8) * 128;
    const int xorC   = lid & 7;
    const int chSelA = lid >> 4;
    const int chSelB = (lid >> 3) & 1;

#pragma unroll
    for (int ks = 0; ks < 4; ks++) {
        const uint32_t chA = (uint32_t)((ks * 2 + chSelA) ^ xorC) << 4;
        const uint32_t chB = (uint32_t)((ks * 2 + chSelB) ^ xorC) << 4;
        uint32_t a[4];
        ldsm4(a, sq + aRowOff + chA);
        uint32_t bh[4][4], bl[4][4];
#pragma unroll
        for (int p = 0; p < 4; p++) {
            ldsm4(bh[p], sbh + bRowOff + p * (16 * 128) + chB);
            ldsm4(bl[p], sbl + bRowOff + p * (16 * 128) + chB);
        }
#pragma unroll
        for (int p = 0; p < 4; p++) {
            hmma(acc[2 * p + 0], a, &bh[p][0]);
            hmma(acc[2 * p + 1], a, &bh[p][2]);
            hmma(acc[2 * p + 0], a, &bl[p][0]);
            hmma(acc[2 * p + 1], a, &bl[p][2]);
        }
    }

    float* obase = out + ((size_t)pair * NSEQ + (size_t)n0) * HDIM;
    const int r0 = wid * 16 + (lid >> 2);
    const int ec = (lid & 3) * 2;
#pragma unroll
    for (int nt = 0; nt < 8; nt++) {
        *(float2*)&obase[(size_t)r0 * HDIM + ec + nt * 8] = *(float2*)&acc[nt][0];
        *(float2*)&obase[(size_t)(r0 + 8) * HDIM + ec + nt * 8] = *(float2*)&acc[nt][2];
    }
}

// ---------------------------------------------------------------------------
// Host launch (6 kernels)
// ---------------------------------------------------------------------------
extern "C" void kernel_launch(void* const* d_in, const int* in_sizes, int n_in,
                              void* d_out, int out_size)
{
    (void)in_sizes; (void)n_in; (void)out_size;
    const float* x    = (const float*)d_in[0];
    const float* W    = (const float*)d_in[1];
    const float* bias = (const float*)d_in[2];
    float* out = (float*)d_out;

    static int attr_set = 0;
    if (!attr_set) {
        cudaFuncSetAttribute(qkv_mma, cudaFuncAttributeMaxDynamicSharedMemorySize, SMEM_DYN);
        cudaFuncSetAttribute(kv_partial, cudaFuncAttributeMaxDynamicSharedMemorySize, KVP_SMEM);
        cudaFuncSetAttribute(out_gemm, cudaFuncAttributeMaxDynamicSharedMemorySize, OUT_SMEM);
        attr_set = 1;
    }

    conv_x<<<(M_ROWS * K_DIM / 4) / 256, 256>>>((const float4*)x);
    conv_w<<<dim3(16, 32), 256>>>(W, bias);

    qkv_mma<<<dim3(N_COLS / QBN, M_ROWS / QBM), 256, SMEM_DYN>>>();

    kv_partial<<<dim3(64, 4), 256, KVP_SMEM>>>();
    kv_reduce<<<256, 256>>>();
    out_gemm<<<dim3(64, 16), 256, OUT_SMEM>>>(out);
}